// round 14
// baseline (speedup 1.0000x reference)
#include <cuda_runtime.h>
#include <cmath>
#include <stdint.h>

#define DMAX 256         // max domains supported
#define SMAX 1024        // max superposition dim supported
#define BPDMAX 64        // max blocks-per-domain in reduce
#define RED_THREADS 256
#define KC 64            // K-chunk for k_out_fast

// Scratch (device globals — no allocation allowed)
__device__ float g_part_sum[DMAX][BPDMAX];
__device__ float g_part_sq [DMAX][BPDMAX];
__device__ float g_cr[DMAX][DMAX];
__device__ float g_ci[DMAX][DMAX];
__device__ float g_Tr[DMAX][SMAX];
__device__ float g_Ti[DMAX][SMAX];

// ---------------------------------------------------------------------------
// Kernel 1: per-(domain, chunk) partial sum + sum-of-squares. HBM streaming.
// EXACT R9 config — measured optimum: 8x front-batched LDG.128, 56 regs,
// __launch_bounds__(256,4), grid 1024 -> 78.0us, 87.4% DRAM, 6926 GB/s.
// (R13 proved 12x/72regs regresses: occ 36% -> 83.6% duty.) DO NOT TOUCH.
// ---------------------------------------------------------------------------
__global__ __launch_bounds__(RED_THREADS, 4)
void k_reduce(const float* __restrict__ vulns, int L, int bpd) {
    const int d   = blockIdx.y;
    const int c   = blockIdx.x;
    const int tid = threadIdx.x;
    const float* __restrict__ base = vulns + (size_t)d * (size_t)L;

    const int span = (L + bpd - 1) / bpd;
    const int s0   = c * span;
    int se = s0 + span; if (se > L) se = L;

    float s1a = 0.f, s1b = 0.f, s1c = 0.f, s1d = 0.f;
    float s2a = 0.f, s2b = 0.f, s2c = 0.f, s2d = 0.f;
    if (s0 < se) {
        uintptr_t addr = (uintptr_t)(base + s0);
        int mis = (int)(((16u - (unsigned)(addr & 15u)) & 15u) >> 2);
        int head_end = s0 + mis; if (head_end > se) head_end = se;
        for (int i = s0 + tid; i < head_end; i += RED_THREADS) {
            float v = base[i]; s1a += v; s2a = fmaf(v, v, s2a);
        }
        const int nvec = (se - head_end) >> 2;
        const float4* __restrict__ vbase = (const float4*)(base + head_end);

        int i = tid;
        for (; i + 7 * RED_THREADS < nvec; i += 8 * RED_THREADS) {
            float4 v0 = __ldcs(vbase + i);
            float4 v1 = __ldcs(vbase + i +     RED_THREADS);
            float4 v2 = __ldcs(vbase + i + 2 * RED_THREADS);
            float4 v3 = __ldcs(vbase + i + 3 * RED_THREADS);
            float4 v4 = __ldcs(vbase + i + 4 * RED_THREADS);
            float4 v5 = __ldcs(vbase + i + 5 * RED_THREADS);
            float4 v6 = __ldcs(vbase + i + 6 * RED_THREADS);
            float4 v7 = __ldcs(vbase + i + 7 * RED_THREADS);
            s1a += (v0.x + v0.y) + (v0.z + v0.w);
            s1b += (v1.x + v1.y) + (v1.z + v1.w);
            s1c += (v2.x + v2.y) + (v2.z + v2.w);
            s1d += (v3.x + v3.y) + (v3.z + v3.w);
            s1a += (v4.x + v4.y) + (v4.z + v4.w);
            s1b += (v5.x + v5.y) + (v5.z + v5.w);
            s1c += (v6.x + v6.y) + (v6.z + v6.w);
            s1d += (v7.x + v7.y) + (v7.z + v7.w);
            s2a += (v0.x * v0.x + v0.y * v0.y) + (v0.z * v0.z + v0.w * v0.w);
            s2b += (v1.x * v1.x + v1.y * v1.y) + (v1.z * v1.z + v1.w * v1.w);
            s2c += (v2.x * v2.x + v2.y * v2.y) + (v2.z * v2.z + v2.w * v2.w);
            s2d += (v3.x * v3.x + v3.y * v3.y) + (v3.z * v3.z + v3.w * v3.w);
            s2a += (v4.x * v4.x + v4.y * v4.y) + (v4.z * v4.z + v4.w * v4.w);
            s2b += (v5.x * v5.x + v5.y * v5.y) + (v5.z * v5.z + v5.w * v5.w);
            s2c += (v6.x * v6.x + v6.y * v6.y) + (v6.z * v6.z + v6.w * v6.w);
            s2d += (v7.x * v7.x + v7.y * v7.y) + (v7.z * v7.z + v7.w * v7.w);
        }
        for (; i < nvec; i += RED_THREADS) {
            float4 v = __ldcs(vbase + i);
            s1a += (v.x + v.y) + (v.z + v.w);
            s2a += (v.x * v.x + v.y * v.y) + (v.z * v.z + v.w * v.w);
        }
        for (int t = head_end + (nvec << 2) + tid; t < se; t += RED_THREADS) {
            float v = base[t]; s1a += v; s2a = fmaf(v, v, s2a);
        }
    }
    float s1 = (s1a + s1b) + (s1c + s1d);
    float s2 = (s2a + s2b) + (s2c + s2d);

    #pragma unroll
    for (int o = 16; o > 0; o >>= 1) {
        s1 += __shfl_down_sync(0xffffffffu, s1, o);
        s2 += __shfl_down_sync(0xffffffffu, s2, o);
    }
    __shared__ float sh1[RED_THREADS / 32], sh2[RED_THREADS / 32];
    if ((tid & 31) == 0) { sh1[tid >> 5] = s1; sh2[tid >> 5] = s2; }
    __syncthreads();
    if (tid == 0) {
        float t1 = 0.f, t2 = 0.f;
        #pragma unroll
        for (int w = 0; w < RED_THREADS / 32; ++w) { t1 += sh1[w]; t2 += sh2[w]; }
        g_part_sum[d][c] = t1;
        g_part_sq [d][c] = t2;
    }
}

// ---------------------------------------------------------------------------
// Kernel 2: FUSED finalize + coeff + T (R13 version — measured good).
// Block (x = chunk of S/2, y = row i). 8-deep independent float2 load batch
// to hide L2 latency in the j-loop.
// coeff identity: cos(atan2(mj,mi))=mi/hyp, sin=mj/hyp, amp=sqrt(pi*pj).
// ---------------------------------------------------------------------------
__global__ __launch_bounds__(256, 4)
void k_T(const float* __restrict__ embed, int D, int S,
         int bpd, float invL, int withImag) {
    const int i   = blockIdx.y;
    const int tid = threadIdx.x;

    __shared__ float sm[DMAX], sp[DMAX];
    __shared__ float scr[DMAX], sci[DMAX];

    for (int j = tid; j < D; j += 256) {
        float s1 = 0.f, s2 = 0.f;
        #pragma unroll 4
        for (int c = 0; c < bpd; ++c) {
            s1 += g_part_sum[j][c];
            s2 += g_part_sq [j][c];
        }
        sm[j] = s1 * invL;
        sp[j] = s2;
    }
    __syncthreads();
    for (int j = tid; j < D; j += 256) {
        float cr = 0.f, ci = 0.f;
        if (j > i) {
            const float mi = sm[i], mj = sm[j];
            const float amp = sqrtf(sp[i] * sp[j]);
            const float inv = rsqrtf(mi * mi + mj * mj);
            cr = amp * mi * inv;
            ci = amp * mj * inv;
        }
        scr[j] = cr;
        sci[j] = ci;
    }
    __syncthreads();
    if (withImag) {
        for (int j = tid; j < D; j += 256) {
            g_cr[i][j] = scr[j];
            g_ci[i][j] = sci[j];
        }
    }

    const int halfS = S >> 1;
    const int s2i = blockIdx.x * 256 + tid;
    if (s2i < halfS) {
        const float2* __restrict__ e2 = (const float2*)embed;
        float2 ar = make_float2(0.f, 0.f);
        float2 ai = make_float2(0.f, 0.f);
        int j = i + 1;
        for (; j + 7 < D; j += 8) {
            const float2 e0 = e2[(size_t)(j    ) * halfS + s2i];
            const float2 e1 = e2[(size_t)(j + 1) * halfS + s2i];
            const float2 e2v= e2[(size_t)(j + 2) * halfS + s2i];
            const float2 e3 = e2[(size_t)(j + 3) * halfS + s2i];
            const float2 e4 = e2[(size_t)(j + 4) * halfS + s2i];
            const float2 e5 = e2[(size_t)(j + 5) * halfS + s2i];
            const float2 e6 = e2[(size_t)(j + 6) * halfS + s2i];
            const float2 e7 = e2[(size_t)(j + 7) * halfS + s2i];
            ar.x = fmaf(scr[j    ], e0.x, ar.x); ar.y = fmaf(scr[j    ], e0.y, ar.y);
            ar.x = fmaf(scr[j + 1], e1.x, ar.x); ar.y = fmaf(scr[j + 1], e1.y, ar.y);
            ar.x = fmaf(scr[j + 2], e2v.x, ar.x); ar.y = fmaf(scr[j + 2], e2v.y, ar.y);
            ar.x = fmaf(scr[j + 3], e3.x, ar.x); ar.y = fmaf(scr[j + 3], e3.y, ar.y);
            ar.x = fmaf(scr[j + 4], e4.x, ar.x); ar.y = fmaf(scr[j + 4], e4.y, ar.y);
            ar.x = fmaf(scr[j + 5], e5.x, ar.x); ar.y = fmaf(scr[j + 5], e5.y, ar.y);
            ar.x = fmaf(scr[j + 6], e6.x, ar.x); ar.y = fmaf(scr[j + 6], e6.y, ar.y);
            ar.x = fmaf(scr[j + 7], e7.x, ar.x); ar.y = fmaf(scr[j + 7], e7.y, ar.y);
            if (withImag) {
                ai.x = fmaf(sci[j    ], e0.x, ai.x); ai.y = fmaf(sci[j    ], e0.y, ai.y);
                ai.x = fmaf(sci[j + 1], e1.x, ai.x); ai.y = fmaf(sci[j + 1], e1.y, ai.y);
                ai.x = fmaf(sci[j + 2], e2v.x, ai.x); ai.y = fmaf(sci[j + 2], e2v.y, ai.y);
                ai.x = fmaf(sci[j + 3], e3.x, ai.x); ai.y = fmaf(sci[j + 3], e3.y, ai.y);
                ai.x = fmaf(sci[j + 4], e4.x, ai.x); ai.y = fmaf(sci[j + 4], e4.y, ai.y);
                ai.x = fmaf(sci[j + 5], e5.x, ai.x); ai.y = fmaf(sci[j + 5], e5.y, ai.y);
                ai.x = fmaf(sci[j + 6], e6.x, ai.x); ai.y = fmaf(sci[j + 6], e6.y, ai.y);
                ai.x = fmaf(sci[j + 7], e7.x, ai.x); ai.y = fmaf(sci[j + 7], e7.y, ai.y);
            }
        }
        for (; j < D; ++j) {
            const float2 e = e2[(size_t)j * halfS + s2i];
            ar.x = fmaf(scr[j], e.x, ar.x);
            ar.y = fmaf(scr[j], e.y, ar.y);
            if (withImag) {
                ai.x = fmaf(sci[j], e.x, ai.x);
                ai.y = fmaf(sci[j], e.y, ai.y);
            }
        }
        ((float2*)g_Tr[i])[s2i] = ar;
        if (withImag) ((float2*)g_Ti[i])[s2i] = ai;
    }
    if ((S & 1) && blockIdx.x == 0 && tid == 0) {
        const int s = S - 1;
        float ar = 0.f, ai = 0.f;
        for (int j = i + 1; j < D; ++j) {
            ar = fmaf(scr[j], embed[(size_t)j * S + s], ar);
            ai = fmaf(sci[j], embed[(size_t)j * S + s], ai);
        }
        g_Tr[i][s] = ar;
        if (withImag) g_Ti[i][s] = ai;
    }
}

// ---------------------------------------------------------------------------
// Kernel 3 (fast path, S%4==0): out = E^T @ Tr, REAL output. PROVEN shape.
// ---------------------------------------------------------------------------
__global__ __launch_bounds__(256)
void k_out_fast(const float* __restrict__ embed, float* __restrict__ out,
                int D, int S) {
    const int tid = threadIdx.x;
    const int tb  = tid & 15;
    const int ta  = tid >> 4;
    const int b0  = blockIdx.x * 64;
    const int a0  = blockIdx.y * 32;

    __shared__ float Es [KC][32];
    __shared__ float Trs[KC][64];

    float a00 = 0.f, a01 = 0.f, a02 = 0.f, a03 = 0.f;
    float a10 = 0.f, a11 = 0.f, a12 = 0.f, a13 = 0.f;

    for (int k0 = 0; k0 < D; k0 += KC) {
        #pragma unroll
        for (int u = 0; u < 2; ++u) {
            const int e = tid + u * 256;
            const int kk = e >> 3, cc = (e & 7) << 2;
            const int k = k0 + kk;
            float4 v = make_float4(0.f, 0.f, 0.f, 0.f);
            if (k < D && a0 + cc + 3 < S)
                v = *(const float4*)&embed[(size_t)k * S + a0 + cc];
            *(float4*)&Es[kk][cc] = v;
        }
        #pragma unroll
        for (int u = 0; u < 4; ++u) {
            const int e = tid + u * 256;
            const int kk = e >> 4, cc = (e & 15) << 2;
            const int k = k0 + kk;
            float4 v = make_float4(0.f, 0.f, 0.f, 0.f);
            if (k < D && b0 + cc + 3 < S)
                v = *(const float4*)&g_Tr[k][b0 + cc];
            *(float4*)&Trs[kk][cc] = v;
        }
        __syncthreads();
        #pragma unroll 8
        for (int kk = 0; kk < KC; ++kk) {
            const float e0 = Es[kk][ta];
            const float e1 = Es[kk][ta + 16];
            const float4 t = *(const float4*)&Trs[kk][tb << 2];
            a00 = fmaf(e0, t.x, a00); a01 = fmaf(e0, t.y, a01);
            a02 = fmaf(e0, t.z, a02); a03 = fmaf(e0, t.w, a03);
            a10 = fmaf(e1, t.x, a10); a11 = fmaf(e1, t.y, a11);
            a12 = fmaf(e1, t.z, a12); a13 = fmaf(e1, t.w, a13);
        }
        __syncthreads();
    }
    const int b = b0 + (tb << 2);
    const int aA = a0 + ta, aB = a0 + ta + 16;
    if (aA < S && b + 3 < S)
        *(float4*)&out[(size_t)aA * S + b] = make_float4(a00, a01, a02, a03);
    if (aB < S && b + 3 < S)
        *(float4*)&out[(size_t)aB * S + b] = make_float4(a10, a11, a12, a13);
}

// ---------------------------------------------------------------------------
// Generic / complex fallbacks.
// ---------------------------------------------------------------------------
__global__ __launch_bounds__(256)
void k_out_gen(const float* __restrict__ embed, float* __restrict__ out,
               int D, int S) {
    const int tx = threadIdx.x, ty = threadIdx.y;
    const int b0 = blockIdx.x * 16, a0 = blockIdx.y * 16;
    __shared__ float Es[16][17], Trs[16][17];
    float ar = 0.f;
    for (int k0 = 0; k0 < D; k0 += 16) {
        const int k = k0 + ty;
        const bool kv = (k < D);
        Es [ty][tx] = (kv && a0 + tx < S) ? embed[(size_t)k * S + a0 + tx] : 0.f;
        Trs[ty][tx] = (kv && b0 + tx < S) ? g_Tr[k][b0 + tx] : 0.f;
        __syncthreads();
        #pragma unroll
        for (int kk = 0; kk < 16; ++kk)
            ar = fmaf(Es[kk][ty], Trs[kk][tx], ar);
        __syncthreads();
    }
    const int a = a0 + ty, b = b0 + tx;
    if (a < S && b < S) out[(size_t)a * S + b] = ar;
}

__global__ __launch_bounds__(256)
void k_out_cplx(const float* __restrict__ embed, float2* __restrict__ out,
                int D, int S) {
    const int tx = threadIdx.x, ty = threadIdx.y;
    const int b0 = blockIdx.x * 16, a0 = blockIdx.y * 16;
    __shared__ float Es[16][17], Trs[16][17], Tis[16][17];
    float ar = 0.f, ai = 0.f;
    for (int k0 = 0; k0 < D; k0 += 16) {
        const int k = k0 + ty;
        const bool kv = (k < D);
        Es [ty][tx] = (kv && a0 + tx < S) ? embed[(size_t)k * S + a0 + tx] : 0.f;
        Trs[ty][tx] = (kv && b0 + tx < S) ? g_Tr[k][b0 + tx] : 0.f;
        Tis[ty][tx] = (kv && b0 + tx < S) ? g_Ti[k][b0 + tx] : 0.f;
        __syncthreads();
        #pragma unroll
        for (int kk = 0; kk < 16; ++kk) {
            const float e = Es[kk][ty];
            ar = fmaf(e, Trs[kk][tx], ar);
            ai = fmaf(e, Tis[kk][tx], ai);
        }
        __syncthreads();
    }
    const int a = a0 + ty, b = b0 + tx;
    if (a < S && b < S) out[(size_t)a * S + b] = make_float2(ar, ai);
}

// ---------------------------------------------------------------------------
static long long isqrt_exact(long long x) {
    if (x <= 0) return -1;
    long long r = (long long)llround(sqrt((double)x));
    for (long long c = r - 2; c <= r + 2; ++c)
        if (c > 0 && c * c == x) return c;
    return -1;
}

extern "C" void kernel_launch(void* const* d_in, const int* in_sizes, int n_in,
                              void* d_out, int out_size) {
    if (n_in < 2) return;

    int mode = 0;
    long long S_ll = isqrt_exact((long long)out_size);
    if (S_ll < 0 && (out_size % 2) == 0) {
        S_ll = isqrt_exact((long long)out_size / 2);
        mode = 1;
    }
    if (S_ll < 1) S_ll = 1;
    int S = (int)S_ll;
    if (S > SMAX) S = SMAX;

    long long sz0 = in_sizes[0], sz1 = in_sizes[1];
    const float* vulns; const float* embed;
    long long vsz, esz;
    if (sz0 >= sz1) { vulns = (const float*)d_in[0]; vsz = sz0;
                      embed = (const float*)d_in[1]; esz = sz1; }
    else            { vulns = (const float*)d_in[1]; vsz = sz1;
                      embed = (const float*)d_in[0]; esz = sz0; }

    int D = (int)(esz / S);
    if (D < 1) D = 1;
    if (D > DMAX) D = DMAX;
    long long L_ll = vsz / D;
    if (L_ll < 1) L_ll = 1;
    int L = (int)L_ll;

    int bpd = (1024 + D - 1) / D;
    if (bpd < 1) bpd = 1;
    if (bpd > BPDMAX) bpd = BPDMAX;

    k_reduce<<<dim3(bpd, D), RED_THREADS>>>(vulns, L, bpd);

    const float invL = 1.0f / (float)L;
    const int halfS = S >> 1;
    int tchunks = (halfS + 255) / 256; if (tchunks < 1) tchunks = 1;
    k_T<<<dim3(tchunks, D), 256>>>(embed, D, S, bpd, invL, mode);

    if (mode == 0) {
        bool fast = ((S & 3) == 0) && (((uintptr_t)embed & 15u) == 0) &&
                    (((uintptr_t)d_out & 15u) == 0);
        if (fast) {
            k_out_fast<<<dim3((S + 63) / 64, (S + 31) / 32), 256>>>(
                embed, (float*)d_out, D, S);
        } else {
            k_out_gen<<<dim3((S + 15) / 16, (S + 15) / 16), dim3(16, 16)>>>(
                embed, (float*)d_out, D, S);
        }
    } else {
        k_out_cplx<<<dim3((S + 15) / 16, (S + 15) / 16), dim3(16, 16)>>>(
            embed, (float2*)d_out, D, S);
    }
}

// round 15
// speedup vs baseline: 1.0694x; 1.0694x over previous
#include <cuda_runtime.h>
#include <cmath>
#include <stdint.h>

#define DMAX 256         // max domains supported
#define SMAX 1024        // max superposition dim supported
#define BPDMAX 64        // max blocks-per-domain in reduce
#define RED_THREADS 256
#define KC 64            // K-chunk for k_out_fast

// Scratch (device globals — no allocation allowed)
__device__ float g_part_sum[DMAX][BPDMAX];
__device__ float g_part_sq [DMAX][BPDMAX];
__device__ float g_cr[DMAX][DMAX];
__device__ float g_ci[DMAX][DMAX];
__device__ float g_Tr[DMAX][SMAX];
__device__ float g_Ti[DMAX][SMAX];

// ---------------------------------------------------------------------------
// Kernel 1: per-(domain, chunk) partial sum + sum-of-squares. HBM streaming.
// PROVEN body (R9): 8x front-batched LDG.128, 56 regs, launch_bounds(256,4).
// NEW: grid sized to ONE TRUE WAVE at the real 4-CTA/SM residency
// (592 slots): bpd=4 -> 512 CTAs, all resident from t=0, no wave transition.
// ---------------------------------------------------------------------------
__global__ __launch_bounds__(RED_THREADS, 4)
void k_reduce(const float* __restrict__ vulns, int L, int bpd) {
    const int d   = blockIdx.y;
    const int c   = blockIdx.x;
    const int tid = threadIdx.x;
    const float* __restrict__ base = vulns + (size_t)d * (size_t)L;

    const int span = (L + bpd - 1) / bpd;
    const int s0   = c * span;
    int se = s0 + span; if (se > L) se = L;

    float s1a = 0.f, s1b = 0.f, s1c = 0.f, s1d = 0.f;
    float s2a = 0.f, s2b = 0.f, s2c = 0.f, s2d = 0.f;
    if (s0 < se) {
        uintptr_t addr = (uintptr_t)(base + s0);
        int mis = (int)(((16u - (unsigned)(addr & 15u)) & 15u) >> 2);
        int head_end = s0 + mis; if (head_end > se) head_end = se;
        for (int i = s0 + tid; i < head_end; i += RED_THREADS) {
            float v = base[i]; s1a += v; s2a = fmaf(v, v, s2a);
        }
        const int nvec = (se - head_end) >> 2;
        const float4* __restrict__ vbase = (const float4*)(base + head_end);

        int i = tid;
        for (; i + 7 * RED_THREADS < nvec; i += 8 * RED_THREADS) {
            float4 v0 = __ldcs(vbase + i);
            float4 v1 = __ldcs(vbase + i +     RED_THREADS);
            float4 v2 = __ldcs(vbase + i + 2 * RED_THREADS);
            float4 v3 = __ldcs(vbase + i + 3 * RED_THREADS);
            float4 v4 = __ldcs(vbase + i + 4 * RED_THREADS);
            float4 v5 = __ldcs(vbase + i + 5 * RED_THREADS);
            float4 v6 = __ldcs(vbase + i + 6 * RED_THREADS);
            float4 v7 = __ldcs(vbase + i + 7 * RED_THREADS);
            s1a += (v0.x + v0.y) + (v0.z + v0.w);
            s1b += (v1.x + v1.y) + (v1.z + v1.w);
            s1c += (v2.x + v2.y) + (v2.z + v2.w);
            s1d += (v3.x + v3.y) + (v3.z + v3.w);
            s1a += (v4.x + v4.y) + (v4.z + v4.w);
            s1b += (v5.x + v5.y) + (v5.z + v5.w);
            s1c += (v6.x + v6.y) + (v6.z + v6.w);
            s1d += (v7.x + v7.y) + (v7.z + v7.w);
            s2a += (v0.x * v0.x + v0.y * v0.y) + (v0.z * v0.z + v0.w * v0.w);
            s2b += (v1.x * v1.x + v1.y * v1.y) + (v1.z * v1.z + v1.w * v1.w);
            s2c += (v2.x * v2.x + v2.y * v2.y) + (v2.z * v2.z + v2.w * v2.w);
            s2d += (v3.x * v3.x + v3.y * v3.y) + (v3.z * v3.z + v3.w * v3.w);
            s2a += (v4.x * v4.x + v4.y * v4.y) + (v4.z * v4.z + v4.w * v4.w);
            s2b += (v5.x * v5.x + v5.y * v5.y) + (v5.z * v5.z + v5.w * v5.w);
            s2c += (v6.x * v6.x + v6.y * v6.y) + (v6.z * v6.z + v6.w * v6.w);
            s2d += (v7.x * v7.x + v7.y * v7.y) + (v7.z * v7.z + v7.w * v7.w);
        }
        for (; i < nvec; i += RED_THREADS) {
            float4 v = __ldcs(vbase + i);
            s1a += (v.x + v.y) + (v.z + v.w);
            s2a += (v.x * v.x + v.y * v.y) + (v.z * v.z + v.w * v.w);
        }
        for (int t = head_end + (nvec << 2) + tid; t < se; t += RED_THREADS) {
            float v = base[t]; s1a += v; s2a = fmaf(v, v, s2a);
        }
    }
    float s1 = (s1a + s1b) + (s1c + s1d);
    float s2 = (s2a + s2b) + (s2c + s2d);

    #pragma unroll
    for (int o = 16; o > 0; o >>= 1) {
        s1 += __shfl_down_sync(0xffffffffu, s1, o);
        s2 += __shfl_down_sync(0xffffffffu, s2, o);
    }
    __shared__ float sh1[RED_THREADS / 32], sh2[RED_THREADS / 32];
    if ((tid & 31) == 0) { sh1[tid >> 5] = s1; sh2[tid >> 5] = s2; }
    __syncthreads();
    if (tid == 0) {
        float t1 = 0.f, t2 = 0.f;
        #pragma unroll
        for (int w = 0; w < RED_THREADS / 32; ++w) { t1 += sh1[w]; t2 += sh2[w]; }
        g_part_sum[d][c] = t1;
        g_part_sq [d][c] = t2;
    }
}

// ---------------------------------------------------------------------------
// Kernel 2: FUSED finalize + coeff + T (best-measured epilogue, R13: 13.9us).
// 8-deep independent float2 load batch hides L2 latency in the j-loop.
// coeff identity: cos(atan2(mj,mi))=mi/hyp, sin=mj/hyp, amp=sqrt(pi*pj).
// ---------------------------------------------------------------------------
__global__ __launch_bounds__(256, 4)
void k_T(const float* __restrict__ embed, int D, int S,
         int bpd, float invL, int withImag) {
    const int i   = blockIdx.y;
    const int tid = threadIdx.x;

    __shared__ float sm[DMAX], sp[DMAX];
    __shared__ float scr[DMAX], sci[DMAX];

    for (int j = tid; j < D; j += 256) {
        float s1 = 0.f, s2 = 0.f;
        #pragma unroll 4
        for (int c = 0; c < bpd; ++c) {
            s1 += g_part_sum[j][c];
            s2 += g_part_sq [j][c];
        }
        sm[j] = s1 * invL;
        sp[j] = s2;
    }
    __syncthreads();
    for (int j = tid; j < D; j += 256) {
        float cr = 0.f, ci = 0.f;
        if (j > i) {
            const float mi = sm[i], mj = sm[j];
            const float amp = sqrtf(sp[i] * sp[j]);
            const float inv = rsqrtf(mi * mi + mj * mj);
            cr = amp * mi * inv;
            ci = amp * mj * inv;
        }
        scr[j] = cr;
        sci[j] = ci;
    }
    __syncthreads();
    if (withImag) {
        for (int j = tid; j < D; j += 256) {
            g_cr[i][j] = scr[j];
            g_ci[i][j] = sci[j];
        }
    }

    const int halfS = S >> 1;
    const int s2i = blockIdx.x * 256 + tid;
    if (s2i < halfS) {
        const float2* __restrict__ e2 = (const float2*)embed;
        float2 ar = make_float2(0.f, 0.f);
        float2 ai = make_float2(0.f, 0.f);
        int j = i + 1;
        for (; j + 7 < D; j += 8) {
            const float2 e0 = e2[(size_t)(j    ) * halfS + s2i];
            const float2 e1 = e2[(size_t)(j + 1) * halfS + s2i];
            const float2 e2v= e2[(size_t)(j + 2) * halfS + s2i];
            const float2 e3 = e2[(size_t)(j + 3) * halfS + s2i];
            const float2 e4 = e2[(size_t)(j + 4) * halfS + s2i];
            const float2 e5 = e2[(size_t)(j + 5) * halfS + s2i];
            const float2 e6 = e2[(size_t)(j + 6) * halfS + s2i];
            const float2 e7 = e2[(size_t)(j + 7) * halfS + s2i];
            ar.x = fmaf(scr[j    ], e0.x, ar.x); ar.y = fmaf(scr[j    ], e0.y, ar.y);
            ar.x = fmaf(scr[j + 1], e1.x, ar.x); ar.y = fmaf(scr[j + 1], e1.y, ar.y);
            ar.x = fmaf(scr[j + 2], e2v.x, ar.x); ar.y = fmaf(scr[j + 2], e2v.y, ar.y);
            ar.x = fmaf(scr[j + 3], e3.x, ar.x); ar.y = fmaf(scr[j + 3], e3.y, ar.y);
            ar.x = fmaf(scr[j + 4], e4.x, ar.x); ar.y = fmaf(scr[j + 4], e4.y, ar.y);
            ar.x = fmaf(scr[j + 5], e5.x, ar.x); ar.y = fmaf(scr[j + 5], e5.y, ar.y);
            ar.x = fmaf(scr[j + 6], e6.x, ar.x); ar.y = fmaf(scr[j + 6], e6.y, ar.y);
            ar.x = fmaf(scr[j + 7], e7.x, ar.x); ar.y = fmaf(scr[j + 7], e7.y, ar.y);
            if (withImag) {
                ai.x = fmaf(sci[j    ], e0.x, ai.x); ai.y = fmaf(sci[j    ], e0.y, ai.y);
                ai.x = fmaf(sci[j + 1], e1.x, ai.x); ai.y = fmaf(sci[j + 1], e1.y, ai.y);
                ai.x = fmaf(sci[j + 2], e2v.x, ai.x); ai.y = fmaf(sci[j + 2], e2v.y, ai.y);
                ai.x = fmaf(sci[j + 3], e3.x, ai.x); ai.y = fmaf(sci[j + 3], e3.y, ai.y);
                ai.x = fmaf(sci[j + 4], e4.x, ai.x); ai.y = fmaf(sci[j + 4], e4.y, ai.y);
                ai.x = fmaf(sci[j + 5], e5.x, ai.x); ai.y = fmaf(sci[j + 5], e5.y, ai.y);
                ai.x = fmaf(sci[j + 6], e6.x, ai.x); ai.y = fmaf(sci[j + 6], e6.y, ai.y);
                ai.x = fmaf(sci[j + 7], e7.x, ai.x); ai.y = fmaf(sci[j + 7], e7.y, ai.y);
            }
        }
        for (; j < D; ++j) {
            const float2 e = e2[(size_t)j * halfS + s2i];
            ar.x = fmaf(scr[j], e.x, ar.x);
            ar.y = fmaf(scr[j], e.y, ar.y);
            if (withImag) {
                ai.x = fmaf(sci[j], e.x, ai.x);
                ai.y = fmaf(sci[j], e.y, ai.y);
            }
        }
        ((float2*)g_Tr[i])[s2i] = ar;
        if (withImag) ((float2*)g_Ti[i])[s2i] = ai;
    }
    if ((S & 1) && blockIdx.x == 0 && tid == 0) {
        const int s = S - 1;
        float ar = 0.f, ai = 0.f;
        for (int j = i + 1; j < D; ++j) {
            ar = fmaf(scr[j], embed[(size_t)j * S + s], ar);
            ai = fmaf(sci[j], embed[(size_t)j * S + s], ai);
        }
        g_Tr[i][s] = ar;
        if (withImag) g_Ti[i][s] = ai;
    }
}

// ---------------------------------------------------------------------------
// Kernel 3 (fast path, S%4==0): out = E^T @ Tr, REAL output. PROVEN shape.
// ---------------------------------------------------------------------------
__global__ __launch_bounds__(256)
void k_out_fast(const float* __restrict__ embed, float* __restrict__ out,
                int D, int S) {
    const int tid = threadIdx.x;
    const int tb  = tid & 15;
    const int ta  = tid >> 4;
    const int b0  = blockIdx.x * 64;
    const int a0  = blockIdx.y * 32;

    __shared__ float Es [KC][32];
    __shared__ float Trs[KC][64];

    float a00 = 0.f, a01 = 0.f, a02 = 0.f, a03 = 0.f;
    float a10 = 0.f, a11 = 0.f, a12 = 0.f, a13 = 0.f;

    for (int k0 = 0; k0 < D; k0 += KC) {
        #pragma unroll
        for (int u = 0; u < 2; ++u) {
            const int e = tid + u * 256;
            const int kk = e >> 3, cc = (e & 7) << 2;
            const int k = k0 + kk;
            float4 v = make_float4(0.f, 0.f, 0.f, 0.f);
            if (k < D && a0 + cc + 3 < S)
                v = *(const float4*)&embed[(size_t)k * S + a0 + cc];
            *(float4*)&Es[kk][cc] = v;
        }
        #pragma unroll
        for (int u = 0; u < 4; ++u) {
            const int e = tid + u * 256;
            const int kk = e >> 4, cc = (e & 15) << 2;
            const int k = k0 + kk;
            float4 v = make_float4(0.f, 0.f, 0.f, 0.f);
            if (k < D && b0 + cc + 3 < S)
                v = *(const float4*)&g_Tr[k][b0 + cc];
            *(float4*)&Trs[kk][cc] = v;
        }
        __syncthreads();
        #pragma unroll 8
        for (int kk = 0; kk < KC; ++kk) {
            const float e0 = Es[kk][ta];
            const float e1 = Es[kk][ta + 16];
            const float4 t = *(const float4*)&Trs[kk][tb << 2];
            a00 = fmaf(e0, t.x, a00); a01 = fmaf(e0, t.y, a01);
            a02 = fmaf(e0, t.z, a02); a03 = fmaf(e0, t.w, a03);
            a10 = fmaf(e1, t.x, a10); a11 = fmaf(e1, t.y, a11);
            a12 = fmaf(e1, t.z, a12); a13 = fmaf(e1, t.w, a13);
        }
        __syncthreads();
    }
    const int b = b0 + (tb << 2);
    const int aA = a0 + ta, aB = a0 + ta + 16;
    if (aA < S && b + 3 < S)
        *(float4*)&out[(size_t)aA * S + b] = make_float4(a00, a01, a02, a03);
    if (aB < S && b + 3 < S)
        *(float4*)&out[(size_t)aB * S + b] = make_float4(a10, a11, a12, a13);
}

// ---------------------------------------------------------------------------
// Generic / complex fallbacks.
// ---------------------------------------------------------------------------
__global__ __launch_bounds__(256)
void k_out_gen(const float* __restrict__ embed, float* __restrict__ out,
               int D, int S) {
    const int tx = threadIdx.x, ty = threadIdx.y;
    const int b0 = blockIdx.x * 16, a0 = blockIdx.y * 16;
    __shared__ float Es[16][17], Trs[16][17];
    float ar = 0.f;
    for (int k0 = 0; k0 < D; k0 += 16) {
        const int k = k0 + ty;
        const bool kv = (k < D);
        Es [ty][tx] = (kv && a0 + tx < S) ? embed[(size_t)k * S + a0 + tx] : 0.f;
        Trs[ty][tx] = (kv && b0 + tx < S) ? g_Tr[k][b0 + tx] : 0.f;
        __syncthreads();
        #pragma unroll
        for (int kk = 0; kk < 16; ++kk)
            ar = fmaf(Es[kk][ty], Trs[kk][tx], ar);
        __syncthreads();
    }
    const int a = a0 + ty, b = b0 + tx;
    if (a < S && b < S) out[(size_t)a * S + b] = ar;
}

__global__ __launch_bounds__(256)
void k_out_cplx(const float* __restrict__ embed, float2* __restrict__ out,
                int D, int S) {
    const int tx = threadIdx.x, ty = threadIdx.y;
    const int b0 = blockIdx.x * 16, a0 = blockIdx.y * 16;
    __shared__ float Es[16][17], Trs[16][17], Tis[16][17];
    float ar = 0.f, ai = 0.f;
    for (int k0 = 0; k0 < D; k0 += 16) {
        const int k = k0 + ty;
        const bool kv = (k < D);
        Es [ty][tx] = (kv && a0 + tx < S) ? embed[(size_t)k * S + a0 + tx] : 0.f;
        Trs[ty][tx] = (kv && b0 + tx < S) ? g_Tr[k][b0 + tx] : 0.f;
        Tis[ty][tx] = (kv && b0 + tx < S) ? g_Ti[k][b0 + tx] : 0.f;
        __syncthreads();
        #pragma unroll
        for (int kk = 0; kk < 16; ++kk) {
            const float e = Es[kk][ty];
            ar = fmaf(e, Trs[kk][tx], ar);
            ai = fmaf(e, Tis[kk][tx], ai);
        }
        __syncthreads();
    }
    const int a = a0 + ty, b = b0 + tx;
    if (a < S && b < S) out[(size_t)a * S + b] = make_float2(ar, ai);
}

// ---------------------------------------------------------------------------
static long long isqrt_exact(long long x) {
    if (x <= 0) return -1;
    long long r = (long long)llround(sqrt((double)x));
    for (long long c = r - 2; c <= r + 2; ++c)
        if (c > 0 && c * c == x) return c;
    return -1;
}

extern "C" void kernel_launch(void* const* d_in, const int* in_sizes, int n_in,
                              void* d_out, int out_size) {
    if (n_in < 2) return;

    int mode = 0;
    long long S_ll = isqrt_exact((long long)out_size);
    if (S_ll < 0 && (out_size % 2) == 0) {
        S_ll = isqrt_exact((long long)out_size / 2);
        mode = 1;
    }
    if (S_ll < 1) S_ll = 1;
    int S = (int)S_ll;
    if (S > SMAX) S = SMAX;

    long long sz0 = in_sizes[0], sz1 = in_sizes[1];
    const float* vulns; const float* embed;
    long long vsz, esz;
    if (sz0 >= sz1) { vulns = (const float*)d_in[0]; vsz = sz0;
                      embed = (const float*)d_in[1]; esz = sz1; }
    else            { vulns = (const float*)d_in[1]; vsz = sz1;
                      embed = (const float*)d_in[0]; esz = sz0; }

    int D = (int)(esz / S);
    if (D < 1) D = 1;
    if (D > DMAX) D = DMAX;
    long long L_ll = vsz / D;
    if (L_ll < 1) L_ll = 1;
    int L = (int)L_ll;

    // Single true wave at 4 CTAs/SM (56 regs): 148*4 = 592 slots.
    // bpd = floor(592 / D): D=128 -> 4 -> 512 CTAs, ALL resident from t=0.
    int bpd = 592 / D;
    if (bpd < 1) bpd = 1;
    if (bpd > BPDMAX) bpd = BPDMAX;

    k_reduce<<<dim3(bpd, D), RED_THREADS>>>(vulns, L, bpd);

    const float invL = 1.0f / (float)L;
    const int halfS = S >> 1;
    int tchunks = (halfS + 255) / 256; if (tchunks < 1) tchunks = 1;
    k_T<<<dim3(tchunks, D), 256>>>(embed, D, S, bpd, invL, mode);

    if (mode == 0) {
        bool fast = ((S & 3) == 0) && (((uintptr_t)embed & 15u) == 0) &&
                    (((uintptr_t)d_out & 15u) == 0);
        if (fast) {
            k_out_fast<<<dim3((S + 63) / 64, (S + 31) / 32), 256>>>(
                embed, (float*)d_out, D, S);
        } else {
            k_out_gen<<<dim3((S + 15) / 16, (S + 15) / 16), dim3(16, 16)>>>(
                embed, (float*)d_out, D, S);
        }
    } else {
        k_out_cplx<<<dim3((S + 15) / 16, (S + 15) / 16), dim3(16, 16)>>>(
            embed, (float2*)d_out, D, S);
    }
}